// round 11
// baseline (speedup 1.0000x reference)
#include <cuda_runtime.h>
#include <cuda_fp16.h>
#include <cstdint>

// Problem constants (fixed shapes)
#define NNODES 100000
#define NEDGES 3200000
#define C 128           // feature dim (in = hid = out = 128)
#define NSCAN_BLOCKS ((NNODES + 1023) / 1024)   // 98
#define ROW_SPLIT (391 * 128)                    // 50048: SpMM1/GEMM2 pipeline split

// ---------------- scratch (static device globals; no allocation) ----------------
// Cleanliness invariants: g_cnt and g_scanFlag must be all-zero at entry.
// Zero-initialized at module load; every call re-zeroes them after use
// (scan_kernel zeroes g_cnt; fill_kernel zeroes g_scanFlag). g_off is
// rewritten by scan_kernel each call before fill consumes it.
__device__ __align__(16) int g_csr[NEDGES];
__device__ int    g_cnt[NNODES];
__device__ int    g_off[NNODES];                // running CSR cursor (starts at rowptr)
__device__ int    g_rowptr[NNODES + 1];
__device__ int    g_scanAgg[NSCAN_BLOCKS];      // block aggregates
__device__ int    g_scanInc[NSCAN_BLOCKS];      // inclusive prefixes
__device__ int    g_scanFlag[NSCAN_BLOCKS];     // 0=none, 1=agg ready, 2=inclusive ready
__device__ float  g_dinv[NNODES];
__device__ __align__(16) __half g_wt1[C * C];   // W1^T fp16 (n-major)
__device__ __align__(16) __half g_wt2[C * C];   // W2^T fp16 (n-major)
__device__ __align__(16) __half g_h[(size_t)NNODES * C];    // dinv-prescaled GEMM out, fp16
__device__ __align__(16) __half g_buf[(size_t)NNODES * C];  // layer-1 agg+relu out, fp16

// dynamic shared memory for the tensor-core GEMM:
//   Xs  : 128 rows x 136 halves (padded: 272B row stride -> conflict-free ldmatrix)
//   Wts : 128 rows x 136 halves
extern __shared__ __align__(16) __half g_smem[];
#define XS_STRIDE 136
#define WTS_OFF   (128 * XS_STRIDE)
#define GEMM_SMEM_BYTES (2 * 128 * XS_STRIDE * (int)sizeof(__half))

// ---------------- mma helpers ----------------
__device__ __forceinline__ unsigned sptr(const void* p) {
    return (unsigned)__cvta_generic_to_shared(p);
}
__device__ __forceinline__ void ldsm_x4(unsigned& r0, unsigned& r1,
                                        unsigned& r2, unsigned& r3, unsigned addr) {
    asm volatile("ldmatrix.sync.aligned.m8n8.x4.shared.b16 {%0,%1,%2,%3}, [%4];"
                 : "=r"(r0), "=r"(r1), "=r"(r2), "=r"(r3) : "r"(addr));
}
__device__ __forceinline__ void mma16816(float& d0, float& d1, float& d2, float& d3,
                                         unsigned a0, unsigned a1, unsigned a2, unsigned a3,
                                         unsigned b0, unsigned b1) {
    asm volatile(
        "mma.sync.aligned.m16n8k16.row.col.f32.f16.f16.f32 "
        "{%0,%1,%2,%3},{%4,%5,%6,%7},{%8,%9},{%0,%1,%2,%3};"
        : "+f"(d0), "+f"(d1), "+f"(d2), "+f"(d3)
        : "r"(a0), "r"(a1), "r"(a2), "r"(a3), "r"(b0), "r"(b1));
}

// ---------------- prologue kernels ----------------

// histogram of dst degree (pure atomics, 4 edges per thread)
__global__ void hist_kernel(const int* __restrict__ ei, int nedges) {
    int t = blockIdx.x * blockDim.x + threadIdx.x;
    int e = t * 4;
    if (e + 4 <= nedges) {
        int4 d4 = *(const int4*)&ei[nedges + e];
        atomicAdd(&g_cnt[d4.x], 1);
        atomicAdd(&g_cnt[d4.y], 1);
        atomicAdd(&g_cnt[d4.z], 1);
        atomicAdd(&g_cnt[d4.w], 1);
    } else {
        for (int k = e; k < nedges; k++) atomicAdd(&g_cnt[ei[nedges + k]], 1);
    }
}

// single-pass exclusive scan (decoupled lookback) + dinv + rowptr[n] + off cursor.
// Also self-cleans g_cnt back to 0 for the next invocation.
__global__ __launch_bounds__(1024) void scan_kernel(int n) {
    __shared__ int warp_sums[32];
    __shared__ int s_agg;
    __shared__ int s_prefix;
    const int tid = threadIdx.x, lane = tid & 31, wid = tid >> 5;
    const int b = blockIdx.x;
    const int i = b * 1024 + tid;
    int v = (i < n) ? g_cnt[i] : 0;
    int x = v;
    #pragma unroll
    for (int off = 1; off < 32; off <<= 1) {
        int t = __shfl_up_sync(0xffffffffu, x, off);
        if (lane >= off) x += t;
    }
    if (lane == 31) warp_sums[wid] = x;
    __syncthreads();
    if (wid == 0) {
        int ws = warp_sums[lane];
        #pragma unroll
        for (int off = 1; off < 32; off <<= 1) {
            int t = __shfl_up_sync(0xffffffffu, ws, off);
            if (lane >= off) ws += t;
        }
        warp_sums[lane] = ws;
    }
    __syncthreads();
    int woff = wid ? warp_sums[wid - 1] : 0;
    if (tid == 1023) s_agg = woff + x;   // block total
    __syncthreads();

    if (tid == 0) {
        int agg = s_agg;
        g_scanAgg[b] = agg;
        __threadfence();
        g_scanFlag[b] = 1;
        // decoupled lookback
        int prefix = 0;
        volatile int* flags = g_scanFlag;
        for (int p = b - 1; p >= 0; p--) {
            int f;
            while ((f = flags[p]) == 0) {}
            if (f == 2) { prefix += g_scanInc[p]; break; }
            prefix += g_scanAgg[p];
        }
        g_scanInc[b] = prefix + agg;
        __threadfence();
        g_scanFlag[b] = 2;
        s_prefix = prefix;
    }
    __syncthreads();
    int prefix = s_prefix;
    if (i < n) {
        int rp = prefix + woff + x - v;          // global exclusive
        g_rowptr[i] = rp;
        g_off[i] = rp;                           // CSR fill cursor
        g_dinv[i] = rsqrtf((float)(v + 1));      // deg = in-deg + self loop
        g_cnt[i] = 0;                            // self-clean for next call
    }
    if (b == gridDim.x - 1 && tid == 1023) g_rowptr[n] = prefix + s_agg;
}

// fill CSR by destination via atomic cursor (4 edges per thread).
// Block 0 also resets the scan flags for the next invocation.
__global__ void fill_kernel(const int* __restrict__ ei, int nedges) {
    if (blockIdx.x == 0 && threadIdx.x < NSCAN_BLOCKS) g_scanFlag[threadIdx.x] = 0;
    int t = blockIdx.x * blockDim.x + threadIdx.x;
    int e = t * 4;
    if (e + 4 <= nedges) {
        int4 s4 = *(const int4*)&ei[e];
        int4 d4 = *(const int4*)&ei[nedges + e];
        g_csr[atomicAdd(&g_off[d4.x], 1)] = s4.x;
        g_csr[atomicAdd(&g_off[d4.y], 1)] = s4.y;
        g_csr[atomicAdd(&g_off[d4.z], 1)] = s4.z;
        g_csr[atomicAdd(&g_off[d4.w], 1)] = s4.w;
    } else {
        for (int k = e; k < nedges; k++)
            g_csr[atomicAdd(&g_off[ei[nedges + k]], 1)] = ei[k];
    }
}

// W1, W2 (fp32 [k][n]) -> g_wt1, g_wt2 (fp16 [n][k]); one launch, 128 blocks.
__global__ void wt_kernel(const float* __restrict__ W1, const float* __restrict__ W2) {
    int i = blockIdx.x * blockDim.x + threadIdx.x;   // 32768 threads
    const float* W = (i < 16384) ? W1 : W2;
    __half* dst = (i < 16384) ? g_wt1 : g_wt2;
    int j = i & 16383;
    int k = j >> 7, n = j & 127;                     // coalesced read
    dst[n * C + k] = __float2half(W[j]);
}

// ---------------- GEMM (tensor core): g_h(fp16) = dinv ⊙ (X @ W) --------------
// Block: 128 rows x 128 cols, K=128 resident. 8 warps: 4 (m) x 2 (n).
// blk0: row-block offset (for the pipelined GEMM2 halves).
template <int LAYER>
__global__ __launch_bounds__(256) void gemm_tc_kernel(
    const float* __restrict__ Xin, int blk0, int nrows) {
    __half* Xs  = g_smem;            // [128][136]
    __half* Wts = g_smem + WTS_OFF;  // [128][136]  (W^T: [n][k])
    const __half* __restrict__ Wg = (LAYER == 1) ? g_wt1 : g_wt2;
    const int tid  = threadIdx.x;
    const int lane = tid & 31;
    const int wid  = tid >> 5;
    const int row_blk = (blockIdx.x + blk0) * 128;

    // load W^T (fp16, 128x128 halves = 2048 uint4)
    #pragma unroll
    for (int i = tid; i < 2048; i += 256) {
        int r = i >> 4, j = i & 15;
        *(uint4*)&Wts[r * XS_STRIDE + j * 8] = ((const uint4*)Wg)[i];
    }
    // X rows into Xs
    if (LAYER == 1) {
        #pragma unroll
        for (int i = tid; i < 4096; i += 256) {       // 128 rows x 32 float4
            int r = i >> 5, j = i & 31;
            int gr = row_blk + r;
            float4 v = (gr < nrows) ? ((const float4*)&Xin[(size_t)gr * C])[j]
                                    : make_float4(0.f, 0.f, 0.f, 0.f);
            __half2 h0 = __floats2half2_rn(v.x, v.y);
            __half2 h1 = __floats2half2_rn(v.z, v.w);
            uint2 st;
            st.x = *(unsigned*)&h0;
            st.y = *(unsigned*)&h1;
            *(uint2*)&Xs[r * XS_STRIDE + j * 4] = st;
        }
    } else {
        #pragma unroll
        for (int i = tid; i < 2048; i += 256) {       // 128 rows x 16 uint4 (fp16)
            int r = i >> 4, j = i & 15;
            int gr = row_blk + r;
            uint4 v = (gr < nrows) ? *(const uint4*)&g_buf[(size_t)gr * C + j * 8]
                                   : make_uint4(0u, 0u, 0u, 0u);
            *(uint4*)&Xs[r * XS_STRIDE + j * 8] = v;
        }
    }
    __syncthreads();

    const int warp_m = wid & 3;        // 4 m-warps -> 32 rows each
    const int warp_n = wid >> 2;       // 2 n-warps -> 64 cols each
    const int m0 = warp_m * 32;
    const int n0 = warp_n * 64;

    float acc[2][8][4];
    #pragma unroll
    for (int mt = 0; mt < 2; mt++)
        #pragma unroll
        for (int nt = 0; nt < 8; nt++)
            #pragma unroll
            for (int q = 0; q < 4; q++) acc[mt][nt][q] = 0.f;

    #pragma unroll
    for (int ks = 0; ks < 8; ks++) {
        const int k0 = ks * 16;
        unsigned A0[4], A1[4];
        {
            const __half* p0 = &Xs[(m0 + 0 + (lane & 15)) * XS_STRIDE + k0 + (lane >> 4) * 8];
            ldsm_x4(A0[0], A0[1], A0[2], A0[3], sptr(p0));
            const __half* p1 = &Xs[(m0 + 16 + (lane & 15)) * XS_STRIDE + k0 + (lane >> 4) * 8];
            ldsm_x4(A1[0], A1[1], A1[2], A1[3], sptr(p1));
        }
        // B: Wts is [n][k] row-major == ".col" B operand -> NON-trans ldmatrix
        unsigned Bf[8][2];
        #pragma unroll
        for (int np = 0; np < 4; np++) {
            int g = lane >> 3;
            const __half* p = &Wts[(n0 + np * 16 + (g >> 1) * 8 + (lane & 7)) * XS_STRIDE
                                   + k0 + (g & 1) * 8];
            unsigned t0, t1, t2, t3;
            ldsm_x4(t0, t1, t2, t3, sptr(p));
            Bf[2 * np + 0][0] = t0; Bf[2 * np + 0][1] = t1;
            Bf[2 * np + 1][0] = t2; Bf[2 * np + 1][1] = t3;
        }
        #pragma unroll
        for (int nt = 0; nt < 8; nt++) {
            mma16816(acc[0][nt][0], acc[0][nt][1], acc[0][nt][2], acc[0][nt][3],
                     A0[0], A0[1], A0[2], A0[3], Bf[nt][0], Bf[nt][1]);
            mma16816(acc[1][nt][0], acc[1][nt][1], acc[1][nt][2], acc[1][nt][3],
                     A1[0], A1[1], A1[2], A1[3], Bf[nt][0], Bf[nt][1]);
        }
    }

    // epilogue: scale row by dinv, store fp16
    #pragma unroll
    for (int mt = 0; mt < 2; mt++) {
        int r0 = row_blk + m0 + mt * 16 + (lane >> 2);
        int r1 = r0 + 8;
        float di0 = (r0 < nrows) ? g_dinv[r0] : 0.f;
        float di1 = (r1 < nrows) ? g_dinv[r1] : 0.f;
        #pragma unroll
        for (int nt = 0; nt < 8; nt++) {
            int col = n0 + nt * 8 + (lane & 3) * 2;
            if (r0 < nrows) {
                __half2 h = __floats2half2_rn(acc[mt][nt][0] * di0, acc[mt][nt][1] * di0);
                *(unsigned*)&g_h[(size_t)r0 * C + col] = *(unsigned*)&h;
            }
            if (r1 < nrows) {
                __half2 h = __floats2half2_rn(acc[mt][nt][2] * di1, acc[mt][nt][3] * di1);
                *(unsigned*)&g_h[(size_t)r1 * C + col] = *(unsigned*)&h;
            }
        }
    }
}

// ---------------- SpMM: warp-per-destination-row, weight-free gather ----------
// out[d] = dinv[d] * ( sum_{e in row d} h'[src_e] + h'[d] ) + bias
// Processes rows [row0, row1). LAYER=1: writes g_buf fp16 (+relu). LAYER=2: fp32 out.
template <int LAYER>
__global__ __launch_bounds__(256) void spmm_kernel(
    const float* __restrict__ bias, float* __restrict__ outp, int row0, int row1) {
    int warp = row0 + ((blockIdx.x * blockDim.x + threadIdx.x) >> 5);
    int lane = threadIdx.x & 31;
    if (warp >= row1) return;
    const uint2* __restrict__ H2 = (const uint2*)g_h;
    float dd = g_dinv[warp];

    float4 acc;
    {
        uint2 raw = __ldcg(&H2[(size_t)warp * 32 + lane]);  // self loop
        float2 f0 = __half22float2(*(const __half2*)&raw.x);
        float2 f1 = __half22float2(*(const __half2*)&raw.y);
        acc = make_float4(f0.x, f0.y, f1.x, f1.y);
    }
    int e0 = g_rowptr[warp];
    int e1 = g_rowptr[warp + 1];
    int e = e0;
    for (; e + 8 <= e1; e += 8) {
        uint2 r[8];
        #pragma unroll
        for (int j = 0; j < 8; j++) {
            int s = g_csr[e + j];
            r[j] = __ldcg(&H2[(size_t)s * 32 + lane]);
        }
        #pragma unroll
        for (int j = 0; j < 8; j++) {
            float2 f0 = __half22float2(*(const __half2*)&r[j].x);
            float2 f1 = __half22float2(*(const __half2*)&r[j].y);
            acc.x += f0.x; acc.y += f0.y; acc.z += f1.x; acc.w += f1.y;
        }
    }
    for (; e < e1; e++) {
        int s = g_csr[e];
        uint2 raw = __ldcg(&H2[(size_t)s * 32 + lane]);
        float2 f0 = __half22float2(*(const __half2*)&raw.x);
        float2 f1 = __half22float2(*(const __half2*)&raw.y);
        acc.x += f0.x; acc.y += f0.y; acc.z += f1.x; acc.w += f1.y;
    }
    float4 b = ((const float4*)bias)[lane];
    acc.x = acc.x * dd + b.x;
    acc.y = acc.y * dd + b.y;
    acc.z = acc.z * dd + b.z;
    acc.w = acc.w * dd + b.w;
    if (LAYER == 1) {
        acc.x = fmaxf(acc.x, 0.f);
        acc.y = fmaxf(acc.y, 0.f);
        acc.z = fmaxf(acc.z, 0.f);
        acc.w = fmaxf(acc.w, 0.f);
        __half2 h0 = __floats2half2_rn(acc.x, acc.y);
        __half2 h1 = __floats2half2_rn(acc.z, acc.w);
        uint2 st;
        st.x = *(unsigned*)&h0;
        st.y = *(unsigned*)&h1;
        ((uint2*)g_buf)[(size_t)warp * 32 + lane] = st;
    } else {
        ((float4*)outp)[(size_t)warp * 32 + lane] = acc;
    }
}

// ---------------- launch (fork/join graph with aux stream) ----------------
static inline int spmm_grid(int rows) { return (rows * 32 + 255) / 256; }

extern "C" void kernel_launch(void* const* d_in, const int* in_sizes, int n_in,
                              void* d_out, int out_size) {
    const float* x  = (const float*)d_in[0];
    const int*   ei = (const int*)d_in[1];     // int32 edge index (2 x E)
    const float* W1 = (const float*)d_in[2];
    const float* b1 = (const float*)d_in[3];
    const float* W2 = (const float*)d_in[4];
    const float* b2 = (const float*)d_in[5];
    float* out = (float*)d_out;

    const int nedges = in_sizes[1] / 2;   // 3,200,000
    const int n = NNODES;

    cudaFuncSetAttribute(gemm_tc_kernel<1>,
                         cudaFuncAttributeMaxDynamicSharedMemorySize, GEMM_SMEM_BYTES);
    cudaFuncSetAttribute(gemm_tc_kernel<2>,
                         cudaFuncAttributeMaxDynamicSharedMemorySize, GEMM_SMEM_BYTES);

    // aux stream + events (host objects; created during the capture call, never
    // destroyed -> become parallel branches of the captured graph)
    cudaStream_t sA;
    cudaStreamCreateWithFlags(&sA, cudaStreamNonBlocking);
    cudaEvent_t evFork, evScan, evG1, evS1lo, evS1hi, evG2;
    cudaEventCreateWithFlags(&evFork, cudaEventDisableTiming);
    cudaEventCreateWithFlags(&evScan, cudaEventDisableTiming);
    cudaEventCreateWithFlags(&evG1,   cudaEventDisableTiming);
    cudaEventCreateWithFlags(&evS1lo, cudaEventDisableTiming);
    cudaEventCreateWithFlags(&evS1hi, cudaEventDisableTiming);
    cudaEventCreateWithFlags(&evG2,   cudaEventDisableTiming);

    // fork aux branch: W transpose is independent of the edge prologue
    cudaEventRecord(evFork, 0);
    cudaStreamWaitEvent(sA, evFork, 0);
    wt_kernel<<<128, 256, 0, sA>>>(W1, W2);

    // main branch: edge prologue
    hist_kernel<<<(nedges / 4 + 255) / 256, 256>>>(ei, nedges);
    scan_kernel<<<NSCAN_BLOCKS, 1024>>>(n);
    cudaEventRecord(evScan, 0);
    fill_kernel<<<(nedges / 4 + 255) / 256, 256>>>(ei, nedges);   // || GEMM1

    // aux: GEMM1 (needs dinv from scan + wt; runs concurrently with fill)
    cudaStreamWaitEvent(sA, evScan, 0);
    gemm_tc_kernel<1><<<782, 256, GEMM_SMEM_BYTES, sA>>>(x, 0, n);
    cudaEventRecord(evG1, sA);

    // main: SpMM1 split at ROW_SPLIT so GEMM2_lo can start early on aux
    cudaStreamWaitEvent(0, evG1, 0);
    spmm_kernel<1><<<spmm_grid(ROW_SPLIT), 256>>>(b1, nullptr, 0, ROW_SPLIT);
    cudaEventRecord(evS1lo, 0);
    spmm_kernel<1><<<spmm_grid(n - ROW_SPLIT), 256>>>(b1, nullptr, ROW_SPLIT, n);
    cudaEventRecord(evS1hi, 0);

    // aux: GEMM2 halves (row-block-local in g_buf)
    cudaStreamWaitEvent(sA, evS1lo, 0);
    gemm_tc_kernel<2><<<391, 256, GEMM_SMEM_BYTES, sA>>>(nullptr, 0, n);
    cudaStreamWaitEvent(sA, evS1hi, 0);
    gemm_tc_kernel<2><<<391, 256, GEMM_SMEM_BYTES, sA>>>(nullptr, 391, n);
    cudaEventRecord(evG2, sA);

    // main: final SpMM (needs all of g_h)
    cudaStreamWaitEvent(0, evG2, 0);
    spmm_kernel<2><<<spmm_grid(n), 256>>>(b2, out, 0, n);
}

// round 12
// speedup vs baseline: 1.0237x; 1.0237x over previous
#include <cuda_runtime.h>
#include <cuda_fp16.h>
#include <cstdint>

// Problem constants (fixed shapes)
#define NNODES 100000
#define NEDGES 3200000
#define C 128           // feature dim (in = hid = out = 128)
#define NSCAN_BLOCKS ((NNODES + 1023) / 1024)   // 98
#define ROW_SPLIT (391 * 128)                    // 50048: SpMM1/GEMM2 pipeline split

// ---------------- scratch (static device globals; no allocation) ----------------
// Cleanliness invariants: g_cnt and g_scanFlag must be all-zero at entry.
// Zero-initialized at module load; every call re-zeroes them after use
// (scan_kernel zeroes g_cnt; fill_kernel zeroes g_scanFlag).
__device__ __align__(16) int g_csr[NEDGES];
__device__ __align__(16) int g_rank[NEDGES];
__device__ int    g_cnt[NNODES];
__device__ int    g_rowptr[NNODES + 1];
__device__ int    g_scanAgg[NSCAN_BLOCKS];      // block aggregates
__device__ int    g_scanInc[NSCAN_BLOCKS];      // inclusive prefixes
__device__ int    g_scanFlag[NSCAN_BLOCKS];     // 0=none, 1=agg ready, 2=inclusive ready
__device__ float  g_dinv[NNODES];
__device__ __align__(16) __half g_wt1[C * C];   // W1^T fp16 (n-major)
__device__ __align__(16) __half g_wt2[C * C];   // W2^T fp16 (n-major)
__device__ __align__(16) __half g_h[(size_t)NNODES * C];    // dinv-prescaled GEMM out, fp16
__device__ __align__(16) __half g_buf[(size_t)NNODES * C];  // layer-1 agg+relu out, fp16

// dynamic shared memory for the tensor-core GEMM:
//   Xs  : 128 rows x 136 halves (padded: 272B row stride -> conflict-free ldmatrix)
//   Wts : 128 rows x 136 halves
extern __shared__ __align__(16) __half g_smem[];
#define XS_STRIDE 136
#define WTS_OFF   (128 * XS_STRIDE)
#define GEMM_SMEM_BYTES (2 * 128 * XS_STRIDE * (int)sizeof(__half))

// ---------------- mma helpers ----------------
__device__ __forceinline__ unsigned sptr(const void* p) {
    return (unsigned)__cvta_generic_to_shared(p);
}
__device__ __forceinline__ void ldsm_x4(unsigned& r0, unsigned& r1,
                                        unsigned& r2, unsigned& r3, unsigned addr) {
    asm volatile("ldmatrix.sync.aligned.m8n8.x4.shared.b16 {%0,%1,%2,%3}, [%4];"
                 : "=r"(r0), "=r"(r1), "=r"(r2), "=r"(r3) : "r"(addr));
}
__device__ __forceinline__ void mma16816(float& d0, float& d1, float& d2, float& d3,
                                         unsigned a0, unsigned a1, unsigned a2, unsigned a3,
                                         unsigned b0, unsigned b1) {
    asm volatile(
        "mma.sync.aligned.m16n8k16.row.col.f32.f16.f16.f32 "
        "{%0,%1,%2,%3},{%4,%5,%6,%7},{%8,%9},{%0,%1,%2,%3};"
        : "+f"(d0), "+f"(d1), "+f"(d2), "+f"(d3)
        : "r"(a0), "r"(a1), "r"(a2), "r"(a3), "r"(b0), "r"(b1));
}

// ---------------- prologue kernels ----------------

// histogram of dst degree + per-edge rank (4 edges per thread)
__global__ void hist_kernel(const int* __restrict__ ei, int nedges) {
    int t = blockIdx.x * blockDim.x + threadIdx.x;
    int e = t * 4;
    if (e + 4 <= nedges) {
        int4 d4 = *(const int4*)&ei[nedges + e];
        int4 r4;
        r4.x = atomicAdd(&g_cnt[d4.x], 1);
        r4.y = atomicAdd(&g_cnt[d4.y], 1);
        r4.z = atomicAdd(&g_cnt[d4.z], 1);
        r4.w = atomicAdd(&g_cnt[d4.w], 1);
        *(int4*)&g_rank[e] = r4;
    } else {
        for (int k = e; k < nedges; k++)
            g_rank[k] = atomicAdd(&g_cnt[ei[nedges + k]], 1);
    }
}

// single-pass exclusive scan (decoupled lookback) + dinv + rowptr[n].
// Also self-cleans g_cnt back to 0 for the next invocation.
__global__ __launch_bounds__(1024) void scan_kernel(int n) {
    __shared__ int warp_sums[32];
    __shared__ int s_agg;
    __shared__ int s_prefix;
    const int tid = threadIdx.x, lane = tid & 31, wid = tid >> 5;
    const int b = blockIdx.x;
    const int i = b * 1024 + tid;
    int v = (i < n) ? g_cnt[i] : 0;
    int x = v;
    #pragma unroll
    for (int off = 1; off < 32; off <<= 1) {
        int t = __shfl_up_sync(0xffffffffu, x, off);
        if (lane >= off) x += t;
    }
    if (lane == 31) warp_sums[wid] = x;
    __syncthreads();
    if (wid == 0) {
        int ws = warp_sums[lane];
        #pragma unroll
        for (int off = 1; off < 32; off <<= 1) {
            int t = __shfl_up_sync(0xffffffffu, ws, off);
            if (lane >= off) ws += t;
        }
        warp_sums[lane] = ws;
    }
    __syncthreads();
    int woff = wid ? warp_sums[wid - 1] : 0;
    if (tid == 1023) s_agg = woff + x;   // block total
    __syncthreads();

    if (tid == 0) {
        int agg = s_agg;
        g_scanAgg[b] = agg;
        __threadfence();
        g_scanFlag[b] = 1;
        // decoupled lookback
        int prefix = 0;
        volatile int* flags = g_scanFlag;
        for (int p = b - 1; p >= 0; p--) {
            int f;
            while ((f = flags[p]) == 0) {}
            if (f == 2) { prefix += g_scanInc[p]; break; }
            prefix += g_scanAgg[p];
        }
        g_scanInc[b] = prefix + agg;
        __threadfence();
        g_scanFlag[b] = 2;
        s_prefix = prefix;
    }
    __syncthreads();
    int prefix = s_prefix;
    if (i < n) {
        g_rowptr[i] = prefix + woff + x - v;     // global exclusive
        g_dinv[i] = rsqrtf((float)(v + 1));      // deg = in-deg + self loop
        g_cnt[i] = 0;                            // self-clean for next call
    }
    if (b == gridDim.x - 1 && tid == 1023) g_rowptr[n] = prefix + s_agg;
}

// fill CSR atomic-free using precomputed ranks (4 edges per thread).
// Block 0 also resets the scan flags for the next invocation.
__global__ void fill_kernel(const int* __restrict__ ei, int nedges) {
    if (blockIdx.x == 0 && threadIdx.x < NSCAN_BLOCKS) g_scanFlag[threadIdx.x] = 0;
    int t = blockIdx.x * blockDim.x + threadIdx.x;
    int e = t * 4;
    if (e + 4 <= nedges) {
        int4 s4 = *(const int4*)&ei[e];
        int4 d4 = *(const int4*)&ei[nedges + e];
        int4 r4 = *(const int4*)&g_rank[e];
        g_csr[g_rowptr[d4.x] + r4.x] = s4.x;
        g_csr[g_rowptr[d4.y] + r4.y] = s4.y;
        g_csr[g_rowptr[d4.z] + r4.z] = s4.z;
        g_csr[g_rowptr[d4.w] + r4.w] = s4.w;
    } else {
        for (int k = e; k < nedges; k++)
            g_csr[g_rowptr[ei[nedges + k]] + g_rank[k]] = ei[k];
    }
}

// W1, W2 (fp32 [k][n]) -> g_wt1, g_wt2 (fp16 [n][k]); one launch, 128 blocks.
__global__ void wt_kernel(const float* __restrict__ W1, const float* __restrict__ W2) {
    int i = blockIdx.x * blockDim.x + threadIdx.x;   // 32768 threads
    const float* W = (i < 16384) ? W1 : W2;
    __half* dst = (i < 16384) ? g_wt1 : g_wt2;
    int j = i & 16383;
    int k = j >> 7, n = j & 127;                     // coalesced read
    dst[n * C + k] = __float2half(W[j]);
}

// ---------------- GEMM (tensor core): g_h(fp16) = dinv ⊙ (X @ W) --------------
// Block: 128 rows x 128 cols, K=128 resident. 8 warps: 4 (m) x 2 (n).
// blk0: row-block offset (for the pipelined GEMM2 halves).
template <int LAYER>
__global__ __launch_bounds__(256) void gemm_tc_kernel(
    const float* __restrict__ Xin, int blk0, int nrows) {
    __half* Xs  = g_smem;            // [128][136]
    __half* Wts = g_smem + WTS_OFF;  // [128][136]  (W^T: [n][k])
    const __half* __restrict__ Wg = (LAYER == 1) ? g_wt1 : g_wt2;
    const int tid  = threadIdx.x;
    const int lane = tid & 31;
    const int wid  = tid >> 5;
    const int row_blk = (blockIdx.x + blk0) * 128;

    // load W^T (fp16, 128x128 halves = 2048 uint4)
    #pragma unroll
    for (int i = tid; i < 2048; i += 256) {
        int r = i >> 4, j = i & 15;
        *(uint4*)&Wts[r * XS_STRIDE + j * 8] = ((const uint4*)Wg)[i];
    }
    // X rows into Xs
    if (LAYER == 1) {
        #pragma unroll
        for (int i = tid; i < 4096; i += 256) {       // 128 rows x 32 float4
            int r = i >> 5, j = i & 31;
            int gr = row_blk + r;
            float4 v = (gr < nrows) ? ((const float4*)&Xin[(size_t)gr * C])[j]
                                    : make_float4(0.f, 0.f, 0.f, 0.f);
            __half2 h0 = __floats2half2_rn(v.x, v.y);
            __half2 h1 = __floats2half2_rn(v.z, v.w);
            uint2 st;
            st.x = *(unsigned*)&h0;
            st.y = *(unsigned*)&h1;
            *(uint2*)&Xs[r * XS_STRIDE + j * 4] = st;
        }
    } else {
        #pragma unroll
        for (int i = tid; i < 2048; i += 256) {       // 128 rows x 16 uint4 (fp16)
            int r = i >> 4, j = i & 15;
            int gr = row_blk + r;
            uint4 v = (gr < nrows) ? *(const uint4*)&g_buf[(size_t)gr * C + j * 8]
                                   : make_uint4(0u, 0u, 0u, 0u);
            *(uint4*)&Xs[r * XS_STRIDE + j * 8] = v;
        }
    }
    __syncthreads();

    const int warp_m = wid & 3;        // 4 m-warps -> 32 rows each
    const int warp_n = wid >> 2;       // 2 n-warps -> 64 cols each
    const int m0 = warp_m * 32;
    const int n0 = warp_n * 64;

    float acc[2][8][4];
    #pragma unroll
    for (int mt = 0; mt < 2; mt++)
        #pragma unroll
        for (int nt = 0; nt < 8; nt++)
            #pragma unroll
            for (int q = 0; q < 4; q++) acc[mt][nt][q] = 0.f;

    #pragma unroll
    for (int ks = 0; ks < 8; ks++) {
        const int k0 = ks * 16;
        unsigned A0[4], A1[4];
        {
            const __half* p0 = &Xs[(m0 + 0 + (lane & 15)) * XS_STRIDE + k0 + (lane >> 4) * 8];
            ldsm_x4(A0[0], A0[1], A0[2], A0[3], sptr(p0));
            const __half* p1 = &Xs[(m0 + 16 + (lane & 15)) * XS_STRIDE + k0 + (lane >> 4) * 8];
            ldsm_x4(A1[0], A1[1], A1[2], A1[3], sptr(p1));
        }
        // B: Wts is [n][k] row-major == ".col" B operand -> NON-trans ldmatrix
        unsigned Bf[8][2];
        #pragma unroll
        for (int np = 0; np < 4; np++) {
            int g = lane >> 3;
            const __half* p = &Wts[(n0 + np * 16 + (g >> 1) * 8 + (lane & 7)) * XS_STRIDE
                                   + k0 + (g & 1) * 8];
            unsigned t0, t1, t2, t3;
            ldsm_x4(t0, t1, t2, t3, sptr(p));
            Bf[2 * np + 0][0] = t0; Bf[2 * np + 0][1] = t1;
            Bf[2 * np + 1][0] = t2; Bf[2 * np + 1][1] = t3;
        }
        #pragma unroll
        for (int nt = 0; nt < 8; nt++) {
            mma16816(acc[0][nt][0], acc[0][nt][1], acc[0][nt][2], acc[0][nt][3],
                     A0[0], A0[1], A0[2], A0[3], Bf[nt][0], Bf[nt][1]);
            mma16816(acc[1][nt][0], acc[1][nt][1], acc[1][nt][2], acc[1][nt][3],
                     A1[0], A1[1], A1[2], A1[3], Bf[nt][0], Bf[nt][1]);
        }
    }

    // epilogue: scale row by dinv, store fp16
    #pragma unroll
    for (int mt = 0; mt < 2; mt++) {
        int r0 = row_blk + m0 + mt * 16 + (lane >> 2);
        int r1 = r0 + 8;
        float di0 = (r0 < nrows) ? g_dinv[r0] : 0.f;
        float di1 = (r1 < nrows) ? g_dinv[r1] : 0.f;
        #pragma unroll
        for (int nt = 0; nt < 8; nt++) {
            int col = n0 + nt * 8 + (lane & 3) * 2;
            if (r0 < nrows) {
                __half2 h = __floats2half2_rn(acc[mt][nt][0] * di0, acc[mt][nt][1] * di0);
                *(unsigned*)&g_h[(size_t)r0 * C + col] = *(unsigned*)&h;
            }
            if (r1 < nrows) {
                __half2 h = __floats2half2_rn(acc[mt][nt][2] * di1, acc[mt][nt][3] * di1);
                *(unsigned*)&g_h[(size_t)r1 * C + col] = *(unsigned*)&h;
            }
        }
    }
}

// ---------------- SpMM: warp-per-destination-row, weight-free gather ----------
// out[d] = dinv[d] * ( sum_{e in row d} h'[src_e] + h'[d] ) + bias
// Processes rows [row0, row1). LAYER=1: writes g_buf fp16 (+relu). LAYER=2: fp32 out.
template <int LAYER>
__global__ __launch_bounds__(256) void spmm_kernel(
    const float* __restrict__ bias, float* __restrict__ outp, int row0, int row1) {
    int warp = row0 + ((blockIdx.x * blockDim.x + threadIdx.x) >> 5);
    int lane = threadIdx.x & 31;
    if (warp >= row1) return;
    const uint2* __restrict__ H2 = (const uint2*)g_h;
    float dd = g_dinv[warp];

    float4 acc;
    {
        uint2 raw = __ldcg(&H2[(size_t)warp * 32 + lane]);  // self loop
        float2 f0 = __half22float2(*(const __half2*)&raw.x);
        float2 f1 = __half22float2(*(const __half2*)&raw.y);
        acc = make_float4(f0.x, f0.y, f1.x, f1.y);
    }
    int e0 = g_rowptr[warp];
    int e1 = g_rowptr[warp + 1];
    int e = e0;
    for (; e + 8 <= e1; e += 8) {
        uint2 r[8];
        #pragma unroll
        for (int j = 0; j < 8; j++) {
            int s = g_csr[e + j];
            r[j] = __ldcg(&H2[(size_t)s * 32 + lane]);
        }
        #pragma unroll
        for (int j = 0; j < 8; j++) {
            float2 f0 = __half22float2(*(const __half2*)&r[j].x);
            float2 f1 = __half22float2(*(const __half2*)&r[j].y);
            acc.x += f0.x; acc.y += f0.y; acc.z += f1.x; acc.w += f1.y;
        }
    }
    for (; e < e1; e++) {
        int s = g_csr[e];
        uint2 raw = __ldcg(&H2[(size_t)s * 32 + lane]);
        float2 f0 = __half22float2(*(const __half2*)&raw.x);
        float2 f1 = __half22float2(*(const __half2*)&raw.y);
        acc.x += f0.x; acc.y += f0.y; acc.z += f1.x; acc.w += f1.y;
    }
    float4 b = ((const float4*)bias)[lane];
    acc.x = acc.x * dd + b.x;
    acc.y = acc.y * dd + b.y;
    acc.z = acc.z * dd + b.z;
    acc.w = acc.w * dd + b.w;
    if (LAYER == 1) {
        acc.x = fmaxf(acc.x, 0.f);
        acc.y = fmaxf(acc.y, 0.f);
        acc.z = fmaxf(acc.z, 0.f);
        acc.w = fmaxf(acc.w, 0.f);
        __half2 h0 = __floats2half2_rn(acc.x, acc.y);
        __half2 h1 = __floats2half2_rn(acc.z, acc.w);
        uint2 st;
        st.x = *(unsigned*)&h0;
        st.y = *(unsigned*)&h1;
        ((uint2*)g_buf)[(size_t)warp * 32 + lane] = st;
    } else {
        ((float4*)outp)[(size_t)warp * 32 + lane] = acc;
    }
}

// ---------------- launch (fork/join graph with aux stream) ----------------
static inline int spmm_grid(int rows) { return (rows * 32 + 255) / 256; }

extern "C" void kernel_launch(void* const* d_in, const int* in_sizes, int n_in,
                              void* d_out, int out_size) {
    const float* x  = (const float*)d_in[0];
    const int*   ei = (const int*)d_in[1];     // int32 edge index (2 x E)
    const float* W1 = (const float*)d_in[2];
    const float* b1 = (const float*)d_in[3];
    const float* W2 = (const float*)d_in[4];
    const float* b2 = (const float*)d_in[5];
    float* out = (float*)d_out;

    const int nedges = in_sizes[1] / 2;   // 3,200,000
    const int n = NNODES;

    cudaFuncSetAttribute(gemm_tc_kernel<1>,
                         cudaFuncAttributeMaxDynamicSharedMemorySize, GEMM_SMEM_BYTES);
    cudaFuncSetAttribute(gemm_tc_kernel<2>,
                         cudaFuncAttributeMaxDynamicSharedMemorySize, GEMM_SMEM_BYTES);

    // aux stream + events (host objects; created during the capture call, never
    // destroyed -> become parallel branches of the captured graph)
    cudaStream_t sA;
    cudaStreamCreateWithFlags(&sA, cudaStreamNonBlocking);
    cudaEvent_t evFork, evScan, evG1, evS1lo, evS1hi, evG2;
    cudaEventCreateWithFlags(&evFork, cudaEventDisableTiming);
    cudaEventCreateWithFlags(&evScan, cudaEventDisableTiming);
    cudaEventCreateWithFlags(&evG1,   cudaEventDisableTiming);
    cudaEventCreateWithFlags(&evS1lo, cudaEventDisableTiming);
    cudaEventCreateWithFlags(&evS1hi, cudaEventDisableTiming);
    cudaEventCreateWithFlags(&evG2,   cudaEventDisableTiming);

    // fork aux branch: W transpose is independent of the edge prologue
    cudaEventRecord(evFork, 0);
    cudaStreamWaitEvent(sA, evFork, 0);
    wt_kernel<<<128, 256, 0, sA>>>(W1, W2);

    // main branch: edge prologue
    hist_kernel<<<(nedges / 4 + 255) / 256, 256>>>(ei, nedges);
    scan_kernel<<<NSCAN_BLOCKS, 1024>>>(n);
    cudaEventRecord(evScan, 0);
    fill_kernel<<<(nedges / 4 + 255) / 256, 256>>>(ei, nedges);   // || GEMM1

    // aux: GEMM1 (needs dinv from scan + wt; runs concurrently with fill)
    cudaStreamWaitEvent(sA, evScan, 0);
    gemm_tc_kernel<1><<<782, 256, GEMM_SMEM_BYTES, sA>>>(x, 0, n);
    cudaEventRecord(evG1, sA);

    // main: SpMM1 split at ROW_SPLIT so GEMM2_lo can start early on aux
    cudaStreamWaitEvent(0, evG1, 0);
    spmm_kernel<1><<<spmm_grid(ROW_SPLIT), 256>>>(b1, nullptr, 0, ROW_SPLIT);
    cudaEventRecord(evS1lo, 0);
    spmm_kernel<1><<<spmm_grid(n - ROW_SPLIT), 256>>>(b1, nullptr, ROW_SPLIT, n);
    cudaEventRecord(evS1hi, 0);

    // aux: GEMM2 halves (row-block-local in g_buf)
    cudaStreamWaitEvent(sA, evS1lo, 0);
    gemm_tc_kernel<2><<<391, 256, GEMM_SMEM_BYTES, sA>>>(nullptr, 0, n);
    cudaStreamWaitEvent(sA, evS1hi, 0);
    gemm_tc_kernel<2><<<391, 256, GEMM_SMEM_BYTES, sA>>>(nullptr, 391, n);
    cudaEventRecord(evG2, sA);

    // main: final SpMM (needs all of g_h)
    cudaStreamWaitEvent(0, evG2, 0);
    spmm_kernel<2><<<spmm_grid(n), 256>>>(b2, out, 0, n);
}

// round 13
// speedup vs baseline: 1.0514x; 1.0271x over previous
#include <cuda_runtime.h>
#include <cuda_fp16.h>
#include <cstdint>

// Problem constants (fixed shapes)
#define NNODES 100000
#define NEDGES 3200000
#define C 128           // feature dim (in = hid = out = 128)
#define NSCAN_BLOCKS ((NNODES + 1023) / 1024)   // 98
#define ROW_SPLIT (391 * 128)                    // 50048: SpMM1/GEMM2 pipeline split

// ---------------- scratch (static device globals; no allocation) ----------------
// Cleanliness invariants: g_cnt and g_scanFlag must be all-zero at entry.
// Zero-initialized at module load; every call re-zeroes them after use
// (scan_kernel zeroes g_cnt; fill_kernel zeroes g_scanFlag).
__device__ __align__(16) int g_csr[NEDGES];
__device__ __align__(16) int g_rank[NEDGES];
__device__ int    g_cnt[NNODES];
__device__ int    g_rowptr[NNODES + 1];
__device__ int    g_scanAgg[NSCAN_BLOCKS];      // block aggregates
__device__ int    g_scanInc[NSCAN_BLOCKS];      // inclusive prefixes
__device__ int    g_scanFlag[NSCAN_BLOCKS];     // 0=none, 1=agg ready, 2=inclusive ready
__device__ float  g_dinv[NNODES];
__device__ __align__(16) __half g_wt1[C * C];   // W1^T fp16 (n-major)
__device__ __align__(16) __half g_wt2[C * C];   // W2^T fp16 (n-major)
__device__ __align__(16) __half g_h[(size_t)NNODES * C];    // GEMM out (dinv-scaled), fp16
__device__ __align__(16) __half g_buf[(size_t)NNODES * C];  // layer-1 agg+relu out, fp16

// dynamic shared memory for the tensor-core GEMM:
//   Xs  : 128 rows x 136 halves (padded: 272B row stride -> conflict-free ldmatrix)
//   Wts : 128 rows x 136 halves
extern __shared__ __align__(16) __half g_smem[];
#define XS_STRIDE 136
#define WTS_OFF   (128 * XS_STRIDE)
#define GEMM_SMEM_BYTES (2 * 128 * XS_STRIDE * (int)sizeof(__half))

// ---------------- mma helpers ----------------
__device__ __forceinline__ unsigned sptr(const void* p) {
    return (unsigned)__cvta_generic_to_shared(p);
}
__device__ __forceinline__ void ldsm_x4(unsigned& r0, unsigned& r1,
                                        unsigned& r2, unsigned& r3, unsigned addr) {
    asm volatile("ldmatrix.sync.aligned.m8n8.x4.shared.b16 {%0,%1,%2,%3}, [%4];"
                 : "=r"(r0), "=r"(r1), "=r"(r2), "=r"(r3) : "r"(addr));
}
__device__ __forceinline__ void mma16816(float& d0, float& d1, float& d2, float& d3,
                                         unsigned a0, unsigned a1, unsigned a2, unsigned a3,
                                         unsigned b0, unsigned b1) {
    asm volatile(
        "mma.sync.aligned.m16n8k16.row.col.f32.f16.f16.f32 "
        "{%0,%1,%2,%3},{%4,%5,%6,%7},{%8,%9},{%0,%1,%2,%3};"
        : "+f"(d0), "+f"(d1), "+f"(d2), "+f"(d3)
        : "r"(a0), "r"(a1), "r"(a2), "r"(a3), "r"(b0), "r"(b1));
}

// ---------------- prologue kernels ----------------

// histogram of dst degree + per-edge rank (4 edges per thread)
__global__ void hist_kernel(const int* __restrict__ ei, int nedges) {
    int t = blockIdx.x * blockDim.x + threadIdx.x;
    int e = t * 4;
    if (e + 4 <= nedges) {
        int4 d4 = *(const int4*)&ei[nedges + e];
        int4 r4;
        r4.x = atomicAdd(&g_cnt[d4.x], 1);
        r4.y = atomicAdd(&g_cnt[d4.y], 1);
        r4.z = atomicAdd(&g_cnt[d4.z], 1);
        r4.w = atomicAdd(&g_cnt[d4.w], 1);
        *(int4*)&g_rank[e] = r4;
    } else {
        for (int k = e; k < nedges; k++)
            g_rank[k] = atomicAdd(&g_cnt[ei[nedges + k]], 1);
    }
}

// single-pass exclusive scan (decoupled lookback) + dinv + rowptr[n].
// Also self-cleans g_cnt back to 0 for the next invocation.
__global__ __launch_bounds__(1024) void scan_kernel(int n) {
    __shared__ int warp_sums[32];
    __shared__ int s_agg;
    __shared__ int s_prefix;
    const int tid = threadIdx.x, lane = tid & 31, wid = tid >> 5;
    const int b = blockIdx.x;
    const int i = b * 1024 + tid;
    int v = (i < n) ? g_cnt[i] : 0;
    int x = v;
    #pragma unroll
    for (int off = 1; off < 32; off <<= 1) {
        int t = __shfl_up_sync(0xffffffffu, x, off);
        if (lane >= off) x += t;
    }
    if (lane == 31) warp_sums[wid] = x;
    __syncthreads();
    if (wid == 0) {
        int ws = warp_sums[lane];
        #pragma unroll
        for (int off = 1; off < 32; off <<= 1) {
            int t = __shfl_up_sync(0xffffffffu, ws, off);
            if (lane >= off) ws += t;
        }
        warp_sums[lane] = ws;
    }
    __syncthreads();
    int woff = wid ? warp_sums[wid - 1] : 0;
    if (tid == 1023) s_agg = woff + x;   // block total
    __syncthreads();

    if (tid == 0) {
        int agg = s_agg;
        g_scanAgg[b] = agg;
        __threadfence();
        g_scanFlag[b] = 1;
        // decoupled lookback
        int prefix = 0;
        volatile int* flags = g_scanFlag;
        for (int p = b - 1; p >= 0; p--) {
            int f;
            while ((f = flags[p]) == 0) {}
            if (f == 2) { prefix += g_scanInc[p]; break; }
            prefix += g_scanAgg[p];
        }
        g_scanInc[b] = prefix + agg;
        __threadfence();
        g_scanFlag[b] = 2;
        s_prefix = prefix;
    }
    __syncthreads();
    int prefix = s_prefix;
    if (i < n) {
        g_rowptr[i] = prefix + woff + x - v;     // global exclusive
        g_dinv[i] = rsqrtf((float)(v + 1));      // deg = in-deg + self loop
        g_cnt[i] = 0;                            // self-clean for next call
    }
    if (b == gridDim.x - 1 && tid == 1023) g_rowptr[n] = prefix + s_agg;
}

// fill CSR atomic-free using precomputed ranks (4 edges per thread).
// Block 0 also resets the scan flags for the next invocation.
__global__ void fill_kernel(const int* __restrict__ ei, int nedges) {
    if (blockIdx.x == 0 && threadIdx.x < NSCAN_BLOCKS) g_scanFlag[threadIdx.x] = 0;
    int t = blockIdx.x * blockDim.x + threadIdx.x;
    int e = t * 4;
    if (e + 4 <= nedges) {
        int4 s4 = *(const int4*)&ei[e];
        int4 d4 = *(const int4*)&ei[nedges + e];
        int4 r4 = *(const int4*)&g_rank[e];
        g_csr[g_rowptr[d4.x] + r4.x] = s4.x;
        g_csr[g_rowptr[d4.y] + r4.y] = s4.y;
        g_csr[g_rowptr[d4.z] + r4.z] = s4.z;
        g_csr[g_rowptr[d4.w] + r4.w] = s4.w;
    } else {
        for (int k = e; k < nedges; k++)
            g_csr[g_rowptr[ei[nedges + k]] + g_rank[k]] = ei[k];
    }
}

// W1, W2 (fp32 [k][n]) -> g_wt1, g_wt2 (fp16 [n][k]); one launch, 128 blocks.
__global__ void wt_kernel(const float* __restrict__ W1, const float* __restrict__ W2) {
    int i = blockIdx.x * blockDim.x + threadIdx.x;   // 32768 threads
    const float* W = (i < 16384) ? W1 : W2;
    __half* dst = (i < 16384) ? g_wt1 : g_wt2;
    int j = i & 16383;
    int k = j >> 7, n = j & 127;                     // coalesced read
    dst[n * C + k] = __float2half(W[j]);
}

// in-place row scale: g_h[row] *= dinv[row]  (fp32 math per element)
// one uint4 (8 halves) per thread; 16 uint4 per row.
__global__ void scale_h_kernel(int n) {
    int idx = blockIdx.x * blockDim.x + threadIdx.x;
    int row = idx >> 4;
    if (row >= n) return;
    float di = g_dinv[row];
    uint4 v = *(uint4*)&g_h[(size_t)idx * 8];
    __half2* h = (__half2*)&v;
    #pragma unroll
    for (int j = 0; j < 4; j++) {
        float2 f = __half22float2(h[j]);
        h[j] = __floats2half2_rn(f.x * di, f.y * di);
    }
    *(uint4*)&g_h[(size_t)idx * 8] = v;
}

// ---------------- GEMM (tensor core): g_h(fp16) = [dinv ⊙] (X @ W) ------------
// Block: 128 rows x 128 cols, K=128 resident. 8 warps: 4 (m) x 2 (n).
// LAYER=1: UNSCALED (dinv applied later by scale_h_kernel -> no scan dependency).
// LAYER=2: dinv folded in epilogue (dinv ready long before).
template <int LAYER>
__global__ __launch_bounds__(256) void gemm_tc_kernel(
    const float* __restrict__ Xin, int blk0, int nrows) {
    __half* Xs  = g_smem;            // [128][136]
    __half* Wts = g_smem + WTS_OFF;  // [128][136]  (W^T: [n][k])
    const __half* __restrict__ Wg = (LAYER == 1) ? g_wt1 : g_wt2;
    const int tid  = threadIdx.x;
    const int lane = tid & 31;
    const int wid  = tid >> 5;
    const int row_blk = (blockIdx.x + blk0) * 128;

    // load W^T (fp16, 128x128 halves = 2048 uint4)
    #pragma unroll
    for (int i = tid; i < 2048; i += 256) {
        int r = i >> 4, j = i & 15;
        *(uint4*)&Wts[r * XS_STRIDE + j * 8] = ((const uint4*)Wg)[i];
    }
    // X rows into Xs
    if (LAYER == 1) {
        #pragma unroll
        for (int i = tid; i < 4096; i += 256) {       // 128 rows x 32 float4
            int r = i >> 5, j = i & 31;
            int gr = row_blk + r;
            float4 v = (gr < nrows) ? ((const float4*)&Xin[(size_t)gr * C])[j]
                                    : make_float4(0.f, 0.f, 0.f, 0.f);
            __half2 h0 = __floats2half2_rn(v.x, v.y);
            __half2 h1 = __floats2half2_rn(v.z, v.w);
            uint2 st;
            st.x = *(unsigned*)&h0;
            st.y = *(unsigned*)&h1;
            *(uint2*)&Xs[r * XS_STRIDE + j * 4] = st;
        }
    } else {
        #pragma unroll
        for (int i = tid; i < 2048; i += 256) {       // 128 rows x 16 uint4 (fp16)
            int r = i >> 4, j = i & 15;
            int gr = row_blk + r;
            uint4 v = (gr < nrows) ? *(const uint4*)&g_buf[(size_t)gr * C + j * 8]
                                   : make_uint4(0u, 0u, 0u, 0u);
            *(uint4*)&Xs[r * XS_STRIDE + j * 8] = v;
        }
    }
    __syncthreads();

    const int warp_m = wid & 3;        // 4 m-warps -> 32 rows each
    const int warp_n = wid >> 2;       // 2 n-warps -> 64 cols each
    const int m0 = warp_m * 32;
    const int n0 = warp_n * 64;

    float acc[2][8][4];
    #pragma unroll
    for (int mt = 0; mt < 2; mt++)
        #pragma unroll
        for (int nt = 0; nt < 8; nt++)
            #pragma unroll
            for (int q = 0; q < 4; q++) acc[mt][nt][q] = 0.f;

    #pragma unroll
    for (int ks = 0; ks < 8; ks++) {
        const int k0 = ks * 16;
        unsigned A0[4], A1[4];
        {
            const __half* p0 = &Xs[(m0 + 0 + (lane & 15)) * XS_STRIDE + k0 + (lane >> 4) * 8];
            ldsm_x4(A0[0], A0[1], A0[2], A0[3], sptr(p0));
            const __half* p1 = &Xs[(m0 + 16 + (lane & 15)) * XS_STRIDE + k0 + (lane >> 4) * 8];
            ldsm_x4(A1[0], A1[1], A1[2], A1[3], sptr(p1));
        }
        // B: Wts is [n][k] row-major == ".col" B operand -> NON-trans ldmatrix
        unsigned Bf[8][2];
        #pragma unroll
        for (int np = 0; np < 4; np++) {
            int g = lane >> 3;
            const __half* p = &Wts[(n0 + np * 16 + (g >> 1) * 8 + (lane & 7)) * XS_STRIDE
                                   + k0 + (g & 1) * 8];
            unsigned t0, t1, t2, t3;
            ldsm_x4(t0, t1, t2, t3, sptr(p));
            Bf[2 * np + 0][0] = t0; Bf[2 * np + 0][1] = t1;
            Bf[2 * np + 1][0] = t2; Bf[2 * np + 1][1] = t3;
        }
        #pragma unroll
        for (int nt = 0; nt < 8; nt++) {
            mma16816(acc[0][nt][0], acc[0][nt][1], acc[0][nt][2], acc[0][nt][3],
                     A0[0], A0[1], A0[2], A0[3], Bf[nt][0], Bf[nt][1]);
            mma16816(acc[1][nt][0], acc[1][nt][1], acc[1][nt][2], acc[1][nt][3],
                     A1[0], A1[1], A1[2], A1[3], Bf[nt][0], Bf[nt][1]);
        }
    }

    // epilogue: (LAYER==2 only) scale row by dinv; store fp16
    #pragma unroll
    for (int mt = 0; mt < 2; mt++) {
        int r0 = row_blk + m0 + mt * 16 + (lane >> 2);
        int r1 = r0 + 8;
        float di0 = 1.f, di1 = 1.f;
        if (LAYER == 2) {
            di0 = (r0 < nrows) ? g_dinv[r0] : 0.f;
            di1 = (r1 < nrows) ? g_dinv[r1] : 0.f;
        }
        #pragma unroll
        for (int nt = 0; nt < 8; nt++) {
            int col = n0 + nt * 8 + (lane & 3) * 2;
            if (r0 < nrows) {
                __half2 h = __floats2half2_rn(acc[mt][nt][0] * di0, acc[mt][nt][1] * di0);
                *(unsigned*)&g_h[(size_t)r0 * C + col] = *(unsigned*)&h;
            }
            if (r1 < nrows) {
                __half2 h = __floats2half2_rn(acc[mt][nt][2] * di1, acc[mt][nt][3] * di1);
                *(unsigned*)&g_h[(size_t)r1 * C + col] = *(unsigned*)&h;
            }
        }
    }
}

// ---------------- SpMM: warp-per-destination-row, weight-free gather ----------
// out[d] = dinv[d] * ( sum_{e in row d} h'[src_e] + h'[d] ) + bias
// Processes rows [row0, row1). LAYER=1: writes g_buf fp16 (+relu). LAYER=2: fp32 out.
template <int LAYER>
__global__ __launch_bounds__(256) void spmm_kernel(
    const float* __restrict__ bias, float* __restrict__ outp, int row0, int row1) {
    int warp = row0 + ((blockIdx.x * blockDim.x + threadIdx.x) >> 5);
    int lane = threadIdx.x & 31;
    if (warp >= row1) return;
    const uint2* __restrict__ H2 = (const uint2*)g_h;
    float dd = g_dinv[warp];

    float4 acc;
    {
        uint2 raw = __ldcg(&H2[(size_t)warp * 32 + lane]);  // self loop
        float2 f0 = __half22float2(*(const __half2*)&raw.x);
        float2 f1 = __half22float2(*(const __half2*)&raw.y);
        acc = make_float4(f0.x, f0.y, f1.x, f1.y);
    }
    int e0 = g_rowptr[warp];
    int e1 = g_rowptr[warp + 1];
    int e = e0;
    for (; e + 8 <= e1; e += 8) {
        uint2 r[8];
        #pragma unroll
        for (int j = 0; j < 8; j++) {
            int s = g_csr[e + j];
            r[j] = __ldcg(&H2[(size_t)s * 32 + lane]);
        }
        #pragma unroll
        for (int j = 0; j < 8; j++) {
            float2 f0 = __half22float2(*(const __half2*)&r[j].x);
            float2 f1 = __half22float2(*(const __half2*)&r[j].y);
            acc.x += f0.x; acc.y += f0.y; acc.z += f1.x; acc.w += f1.y;
        }
    }
    for (; e < e1; e++) {
        int s = g_csr[e];
        uint2 raw = __ldcg(&H2[(size_t)s * 32 + lane]);
        float2 f0 = __half22float2(*(const __half2*)&raw.x);
        float2 f1 = __half22float2(*(const __half2*)&raw.y);
        acc.x += f0.x; acc.y += f0.y; acc.z += f1.x; acc.w += f1.y;
    }
    float4 b = ((const float4*)bias)[lane];
    acc.x = acc.x * dd + b.x;
    acc.y = acc.y * dd + b.y;
    acc.z = acc.z * dd + b.z;
    acc.w = acc.w * dd + b.w;
    if (LAYER == 1) {
        acc.x = fmaxf(acc.x, 0.f);
        acc.y = fmaxf(acc.y, 0.f);
        acc.z = fmaxf(acc.z, 0.f);
        acc.w = fmaxf(acc.w, 0.f);
        __half2 h0 = __floats2half2_rn(acc.x, acc.y);
        __half2 h1 = __floats2half2_rn(acc.z, acc.w);
        uint2 st;
        st.x = *(unsigned*)&h0;
        st.y = *(unsigned*)&h1;
        ((uint2*)g_buf)[(size_t)warp * 32 + lane] = st;
    } else {
        ((float4*)outp)[(size_t)warp * 32 + lane] = acc;
    }
}

// ---------------- launch (fork/join graph with aux stream) ----------------
static inline int spmm_grid(int rows) { return (rows * 32 + 255) / 256; }

extern "C" void kernel_launch(void* const* d_in, const int* in_sizes, int n_in,
                              void* d_out, int out_size) {
    const float* x  = (const float*)d_in[0];
    const int*   ei = (const int*)d_in[1];     // int32 edge index (2 x E)
    const float* W1 = (const float*)d_in[2];
    const float* b1 = (const float*)d_in[3];
    const float* W2 = (const float*)d_in[4];
    const float* b2 = (const float*)d_in[5];
    float* out = (float*)d_out;

    const int nedges = in_sizes[1] / 2;   // 3,200,000
    const int n = NNODES;

    cudaFuncSetAttribute(gemm_tc_kernel<1>,
                         cudaFuncAttributeMaxDynamicSharedMemorySize, GEMM_SMEM_BYTES);
    cudaFuncSetAttribute(gemm_tc_kernel<2>,
                         cudaFuncAttributeMaxDynamicSharedMemorySize, GEMM_SMEM_BYTES);

    // aux stream + events (host objects; created during the capture call, never
    // destroyed -> become parallel branches of the captured graph)
    cudaStream_t sA;
    cudaStreamCreateWithFlags(&sA, cudaStreamNonBlocking);
    cudaEvent_t evFork, evScan, evScaled, evS1lo, evS1hi, evG2;
    cudaEventCreateWithFlags(&evFork,   cudaEventDisableTiming);
    cudaEventCreateWithFlags(&evScan,   cudaEventDisableTiming);
    cudaEventCreateWithFlags(&evScaled, cudaEventDisableTiming);
    cudaEventCreateWithFlags(&evS1lo,   cudaEventDisableTiming);
    cudaEventCreateWithFlags(&evS1hi,   cudaEventDisableTiming);
    cudaEventCreateWithFlags(&evG2,     cudaEventDisableTiming);

    // fork aux branch at t=0: wt + UNSCALED GEMM1 (no edge-prologue dependency)
    cudaEventRecord(evFork, 0);
    cudaStreamWaitEvent(sA, evFork, 0);
    wt_kernel<<<128, 256, 0, sA>>>(W1, W2);
    gemm_tc_kernel<1><<<782, 256, GEMM_SMEM_BYTES, sA>>>(x, 0, n);  // || hist

    // main branch: edge prologue
    hist_kernel<<<(nedges / 4 + 255) / 256, 256>>>(ei, nedges);
    scan_kernel<<<NSCAN_BLOCKS, 1024>>>(n);
    cudaEventRecord(evScan, 0);
    fill_kernel<<<(nedges / 4 + 255) / 256, 256>>>(ei, nedges);     // || scale_h

    // aux: scale g_h by dinv (needs scan + GEMM1); runs concurrently with fill
    cudaStreamWaitEvent(sA, evScan, 0);
    scale_h_kernel<<<(n * 16 + 255) / 256, 256, 0, sA>>>(n);
    cudaEventRecord(evScaled, sA);

    // main: SpMM1 split at ROW_SPLIT so GEMM2_lo can start early on aux
    cudaStreamWaitEvent(0, evScaled, 0);
    spmm_kernel<1><<<spmm_grid(ROW_SPLIT), 256>>>(b1, nullptr, 0, ROW_SPLIT);
    cudaEventRecord(evS1lo, 0);
    spmm_kernel<1><<<spmm_grid(n - ROW_SPLIT), 256>>>(b1, nullptr, ROW_SPLIT, n);
    cudaEventRecord(evS1hi, 0);

    // aux: GEMM2 halves (row-block-local in g_buf)
    cudaStreamWaitEvent(sA, evS1lo, 0);
    gemm_tc_kernel<2><<<391, 256, GEMM_SMEM_BYTES, sA>>>(nullptr, 0, n);
    cudaStreamWaitEvent(sA, evS1hi, 0);
    gemm_tc_kernel<2><<<391, 256, GEMM_SMEM_BYTES, sA>>>(nullptr, 391, n);
    cudaEventRecord(evG2, sA);

    // main: final SpMM (needs all of g_h)
    cudaStreamWaitEvent(0, evG2, 0);
    spmm_kernel<2><<<spmm_grid(n), 256>>>(b2, out, 0, n);
}

// round 14
// speedup vs baseline: 1.0695x; 1.0173x over previous
#include <cuda_runtime.h>
#include <cuda_fp16.h>
#include <cstdint>

// Problem constants (fixed shapes)
#define NNODES 100000
#define NEDGES 3200000
#define C 128           // feature dim (in = hid = out = 128)
#define CAP 128         // fixed CSR row capacity (Poisson(32) in-degree; P(deg>=128)<1e-60)
#define ROW_SPLIT (391 * 128)   // 50048: SpMM1/GEMM2 pipeline split

// ---------------- scratch (static device globals; no allocation) ----------------
// Cleanliness invariant: g_cnt must be all-zero at entry. Zero-init at module
// load; scale_h_kernel re-zeroes it every call after consuming it.
__device__ int    g_csr[(size_t)NNODES * CAP];  // fixed-stride CSR (51.2 MB)
__device__ int    g_cnt[NNODES];
__device__ int    g_deg[NNODES];
__device__ float  g_dinv[NNODES];
__device__ __align__(16) __half g_wt1[C * C];   // W1^T fp16 (n-major)
__device__ __align__(16) __half g_wt2[C * C];   // W2^T fp16 (n-major)
__device__ __align__(16) __half g_h[(size_t)NNODES * C];    // GEMM out (dinv-scaled), fp16
__device__ __align__(16) __half g_buf[(size_t)NNODES * C];  // layer-1 agg+relu out, fp16

// dynamic shared memory for the tensor-core GEMM:
//   Xs  : 128 rows x 136 halves (padded: 272B row stride -> conflict-free ldmatrix)
//   Wts : 128 rows x 136 halves
extern __shared__ __align__(16) __half g_smem[];
#define XS_STRIDE 136
#define WTS_OFF   (128 * XS_STRIDE)
#define GEMM_SMEM_BYTES (2 * 128 * XS_STRIDE * (int)sizeof(__half))

// ---------------- mma helpers ----------------
__device__ __forceinline__ unsigned sptr(const void* p) {
    return (unsigned)__cvta_generic_to_shared(p);
}
__device__ __forceinline__ void ldsm_x4(unsigned& r0, unsigned& r1,
                                        unsigned& r2, unsigned& r3, unsigned addr) {
    asm volatile("ldmatrix.sync.aligned.m8n8.x4.shared.b16 {%0,%1,%2,%3}, [%4];"
                 : "=r"(r0), "=r"(r1), "=r"(r2), "=r"(r3) : "r"(addr));
}
__device__ __forceinline__ void mma16816(float& d0, float& d1, float& d2, float& d3,
                                         unsigned a0, unsigned a1, unsigned a2, unsigned a3,
                                         unsigned b0, unsigned b1) {
    asm volatile(
        "mma.sync.aligned.m16n8k16.row.col.f32.f16.f16.f32 "
        "{%0,%1,%2,%3},{%4,%5,%6,%7},{%8,%9},{%0,%1,%2,%3};"
        : "+f"(d0), "+f"(d1), "+f"(d2), "+f"(d3)
        : "r"(a0), "r"(a1), "r"(a2), "r"(a3), "r"(b0), "r"(b1));
}

// ---------------- prologue kernels ----------------

// one-pass CSR build: rank via atomic, direct scatter into fixed-stride rows.
__global__ void hist_scatter_kernel(const int* __restrict__ ei, int nedges) {
    int t = blockIdx.x * blockDim.x + threadIdx.x;
    int e = t * 4;
    if (e + 4 <= nedges) {
        int4 s4 = *(const int4*)&ei[e];
        int4 d4 = *(const int4*)&ei[nedges + e];
        int r;
        r = atomicAdd(&g_cnt[d4.x], 1); if (r < CAP) g_csr[((size_t)d4.x << 7) + r] = s4.x;
        r = atomicAdd(&g_cnt[d4.y], 1); if (r < CAP) g_csr[((size_t)d4.y << 7) + r] = s4.y;
        r = atomicAdd(&g_cnt[d4.z], 1); if (r < CAP) g_csr[((size_t)d4.z << 7) + r] = s4.z;
        r = atomicAdd(&g_cnt[d4.w], 1); if (r < CAP) g_csr[((size_t)d4.w << 7) + r] = s4.w;
    } else {
        for (int k = e; k < nedges; k++) {
            int d = ei[nedges + k];
            int r = atomicAdd(&g_cnt[d], 1);
            if (r < CAP) g_csr[((size_t)d << 7) + r] = ei[k];
        }
    }
}

// W1, W2 (fp32 [k][n]) -> g_wt1, g_wt2 (fp16 [n][k]); one launch, 128 blocks.
__global__ void wt_kernel(const float* __restrict__ W1, const float* __restrict__ W2) {
    int i = blockIdx.x * blockDim.x + threadIdx.x;   // 32768 threads
    const float* W = (i < 16384) ? W1 : W2;
    __half* dst = (i < 16384) ? g_wt1 : g_wt2;
    int j = i & 16383;
    int k = j >> 7, n = j & 127;                     // coalesced read
    dst[n * C + k] = __float2half(W[j]);
}

// fused: dinv = rsqrt(cnt+1), deg = cnt, cnt = 0 (self-clean), g_h *= dinv.
// 16 threads per row (one uint4 = 8 halves each); row's 16 threads share a warp,
// so the load of g_cnt (all lanes) precedes the lane-0 store in program order.
__global__ void scale_h_kernel(int n) {
    int idx = blockIdx.x * blockDim.x + threadIdx.x;
    int row = idx >> 4;
    if (row >= n) return;
    int c = g_cnt[row];
    float di = rsqrtf((float)(c + 1));
    if ((idx & 15) == 0) {
        g_dinv[row] = di;
        g_deg[row] = c;
        g_cnt[row] = 0;     // self-clean for next call
    }
    uint4 v = *(uint4*)&g_h[(size_t)idx * 8];
    __half2* h = (__half2*)&v;
    #pragma unroll
    for (int j = 0; j < 4; j++) {
        float2 f = __half22float2(h[j]);
        h[j] = __floats2half2_rn(f.x * di, f.y * di);
    }
    *(uint4*)&g_h[(size_t)idx * 8] = v;
}

// ---------------- GEMM (tensor core): g_h(fp16) = [dinv ⊙] (X @ W) ------------
// Block: 128 rows x 128 cols, K=128 resident. 8 warps: 4 (m) x 2 (n).
// LAYER=1: UNSCALED (dinv applied later by scale_h_kernel -> no prologue dep).
// LAYER=2: dinv folded in epilogue (dinv ready long before).
template <int LAYER>
__global__ __launch_bounds__(256) void gemm_tc_kernel(
    const float* __restrict__ Xin, int blk0, int nrows) {
    __half* Xs  = g_smem;            // [128][136]
    __half* Wts = g_smem + WTS_OFF;  // [128][136]  (W^T: [n][k])
    const __half* __restrict__ Wg = (LAYER == 1) ? g_wt1 : g_wt2;
    const int tid  = threadIdx.x;
    const int lane = tid & 31;
    const int wid  = tid >> 5;
    const int row_blk = (blockIdx.x + blk0) * 128;

    // load W^T (fp16, 128x128 halves = 2048 uint4)
    #pragma unroll
    for (int i = tid; i < 2048; i += 256) {
        int r = i >> 4, j = i & 15;
        *(uint4*)&Wts[r * XS_STRIDE + j * 8] = ((const uint4*)Wg)[i];
    }
    // X rows into Xs
    if (LAYER == 1) {
        #pragma unroll
        for (int i = tid; i < 4096; i += 256) {       // 128 rows x 32 float4
            int r = i >> 5, j = i & 31;
            int gr = row_blk + r;
            float4 v = (gr < nrows) ? ((const float4*)&Xin[(size_t)gr * C])[j]
                                    : make_float4(0.f, 0.f, 0.f, 0.f);
            __half2 h0 = __floats2half2_rn(v.x, v.y);
            __half2 h1 = __floats2half2_rn(v.z, v.w);
            uint2 st;
            st.x = *(unsigned*)&h0;
            st.y = *(unsigned*)&h1;
            *(uint2*)&Xs[r * XS_STRIDE + j * 4] = st;
        }
    } else {
        #pragma unroll
        for (int i = tid; i < 2048; i += 256) {       // 128 rows x 16 uint4 (fp16)
            int r = i >> 4, j = i & 15;
            int gr = row_blk + r;
            uint4 v = (gr < nrows) ? *(const uint4*)&g_buf[(size_t)gr * C + j * 8]
                                   : make_uint4(0u, 0u, 0u, 0u);
            *(uint4*)&Xs[r * XS_STRIDE + j * 8] = v;
        }
    }
    __syncthreads();

    const int warp_m = wid & 3;        // 4 m-warps -> 32 rows each
    const int warp_n = wid >> 2;       // 2 n-warps -> 64 cols each
    const int m0 = warp_m * 32;
    const int n0 = warp_n * 64;

    float acc[2][8][4];
    #pragma unroll
    for (int mt = 0; mt < 2; mt++)
        #pragma unroll
        for (int nt = 0; nt < 8; nt++)
            #pragma unroll
            for (int q = 0; q < 4; q++) acc[mt][nt][q] = 0.f;

    #pragma unroll
    for (int ks = 0; ks < 8; ks++) {
        const int k0 = ks * 16;
        unsigned A0[4], A1[4];
        {
            const __half* p0 = &Xs[(m0 + 0 + (lane & 15)) * XS_STRIDE + k0 + (lane >> 4) * 8];
            ldsm_x4(A0[0], A0[1], A0[2], A0[3], sptr(p0));
            const __half* p1 = &Xs[(m0 + 16 + (lane & 15)) * XS_STRIDE + k0 + (lane >> 4) * 8];
            ldsm_x4(A1[0], A1[1], A1[2], A1[3], sptr(p1));
        }
        // B: Wts is [n][k] row-major == ".col" B operand -> NON-trans ldmatrix
        unsigned Bf[8][2];
        #pragma unroll
        for (int np = 0; np < 4; np++) {
            int g = lane >> 3;
            const __half* p = &Wts[(n0 + np * 16 + (g >> 1) * 8 + (lane & 7)) * XS_STRIDE
                                   + k0 + (g & 1) * 8];
            unsigned t0, t1, t2, t3;
            ldsm_x4(t0, t1, t2, t3, sptr(p));
            Bf[2 * np + 0][0] = t0; Bf[2 * np + 0][1] = t1;
            Bf[2 * np + 1][0] = t2; Bf[2 * np + 1][1] = t3;
        }
        #pragma unroll
        for (int nt = 0; nt < 8; nt++) {
            mma16816(acc[0][nt][0], acc[0][nt][1], acc[0][nt][2], acc[0][nt][3],
                     A0[0], A0[1], A0[2], A0[3], Bf[nt][0], Bf[nt][1]);
            mma16816(acc[1][nt][0], acc[1][nt][1], acc[1][nt][2], acc[1][nt][3],
                     A1[0], A1[1], A1[2], A1[3], Bf[nt][0], Bf[nt][1]);
        }
    }

    // epilogue: (LAYER==2 only) scale row by dinv; store fp16
    #pragma unroll
    for (int mt = 0; mt < 2; mt++) {
        int r0 = row_blk + m0 + mt * 16 + (lane >> 2);
        int r1 = r0 + 8;
        float di0 = 1.f, di1 = 1.f;
        if (LAYER == 2) {
            di0 = (r0 < nrows) ? g_dinv[r0] : 0.f;
            di1 = (r1 < nrows) ? g_dinv[r1] : 0.f;
        }
        #pragma unroll
        for (int nt = 0; nt < 8; nt++) {
            int col = n0 + nt * 8 + (lane & 3) * 2;
            if (r0 < nrows) {
                __half2 h = __floats2half2_rn(acc[mt][nt][0] * di0, acc[mt][nt][1] * di0);
                *(unsigned*)&g_h[(size_t)r0 * C + col] = *(unsigned*)&h;
            }
            if (r1 < nrows) {
                __half2 h = __floats2half2_rn(acc[mt][nt][2] * di1, acc[mt][nt][3] * di1);
                *(unsigned*)&g_h[(size_t)r1 * C + col] = *(unsigned*)&h;
            }
        }
    }
}

// ---------------- SpMM: warp-per-destination-row, fixed-stride CSR ------------
// out[d] = dinv[d] * ( sum_{e<deg[d]} h'[csr[d*CAP+e]] + h'[d] ) + bias
// Processes rows [row0, row1). LAYER=1: writes g_buf fp16 (+relu). LAYER=2: fp32 out.
template <int LAYER>
__global__ __launch_bounds__(256) void spmm_kernel(
    const float* __restrict__ bias, float* __restrict__ outp, int row0, int row1) {
    int warp = row0 + ((blockIdx.x * blockDim.x + threadIdx.x) >> 5);
    int lane = threadIdx.x & 31;
    if (warp >= row1) return;
    const uint2* __restrict__ H2 = (const uint2*)g_h;
    const int* __restrict__ row = &g_csr[(size_t)warp << 7];
    float dd = g_dinv[warp];
    int deg = g_deg[warp];

    float4 acc;
    {
        uint2 raw = __ldcg(&H2[(size_t)warp * 32 + lane]);  // self loop
        float2 f0 = __half22float2(*(const __half2*)&raw.x);
        float2 f1 = __half22float2(*(const __half2*)&raw.y);
        acc = make_float4(f0.x, f0.y, f1.x, f1.y);
    }
    int e = 0;
    for (; e + 8 <= deg; e += 8) {
        uint2 r[8];
        #pragma unroll
        for (int j = 0; j < 8; j++) {
            int s = row[e + j];
            r[j] = __ldcg(&H2[(size_t)s * 32 + lane]);
        }
        #pragma unroll
        for (int j = 0; j < 8; j++) {
            float2 f0 = __half22float2(*(const __half2*)&r[j].x);
            float2 f1 = __half22float2(*(const __half2*)&r[j].y);
            acc.x += f0.x; acc.y += f0.y; acc.z += f1.x; acc.w += f1.y;
        }
    }
    for (; e < deg; e++) {
        int s = row[e];
        uint2 raw = __ldcg(&H2[(size_t)s * 32 + lane]);
        float2 f0 = __half22float2(*(const __half2*)&raw.x);
        float2 f1 = __half22float2(*(const __half2*)&raw.y);
        acc.x += f0.x; acc.y += f0.y; acc.z += f1.x; acc.w += f1.y;
    }
    float4 b = ((const float4*)bias)[lane];
    acc.x = acc.x * dd + b.x;
    acc.y = acc.y * dd + b.y;
    acc.z = acc.z * dd + b.z;
    acc.w = acc.w * dd + b.w;
    if (LAYER == 1) {
        acc.x = fmaxf(acc.x, 0.f);
        acc.y = fmaxf(acc.y, 0.f);
        acc.z = fmaxf(acc.z, 0.f);
        acc.w = fmaxf(acc.w, 0.f);
        __half2 h0 = __floats2half2_rn(acc.x, acc.y);
        __half2 h1 = __floats2half2_rn(acc.z, acc.w);
        uint2 st;
        st.x = *(unsigned*)&h0;
        st.y = *(unsigned*)&h1;
        ((uint2*)g_buf)[(size_t)warp * 32 + lane] = st;
    } else {
        ((float4*)outp)[(size_t)warp * 32 + lane] = acc;
    }
}

// ---------------- launch (fork/join graph with aux stream) ----------------
static inline int spmm_grid(int rows) { return (rows * 32 + 255) / 256; }

extern "C" void kernel_launch(void* const* d_in, const int* in_sizes, int n_in,
                              void* d_out, int out_size) {
    const float* x  = (const float*)d_in[0];
    const int*   ei = (const int*)d_in[1];     // int32 edge index (2 x E)
    const float* W1 = (const float*)d_in[2];
    const float* b1 = (const float*)d_in[3];
    const float* W2 = (const float*)d_in[4];
    const float* b2 = (const float*)d_in[5];
    float* out = (float*)d_out;

    const int nedges = in_sizes[1] / 2;   // 3,200,000
    const int n = NNODES;

    cudaFuncSetAttribute(gemm_tc_kernel<1>,
                         cudaFuncAttributeMaxDynamicSharedMemorySize, GEMM_SMEM_BYTES);
    cudaFuncSetAttribute(gemm_tc_kernel<2>,
                         cudaFuncAttributeMaxDynamicSharedMemorySize, GEMM_SMEM_BYTES);

    // aux stream + events (host objects; created during the capture call, never
    // destroyed -> become parallel branches of the captured graph)
    cudaStream_t sA;
    cudaStreamCreateWithFlags(&sA, cudaStreamNonBlocking);
    cudaEvent_t evFork, evHist, evScaled, evS1lo, evS1hi, evG2;
    cudaEventCreateWithFlags(&evFork,   cudaEventDisableTiming);
    cudaEventCreateWithFlags(&evHist,   cudaEventDisableTiming);
    cudaEventCreateWithFlags(&evScaled, cudaEventDisableTiming);
    cudaEventCreateWithFlags(&evS1lo,   cudaEventDisableTiming);
    cudaEventCreateWithFlags(&evS1hi,   cudaEventDisableTiming);
    cudaEventCreateWithFlags(&evG2,     cudaEventDisableTiming);

    // fork aux branch at t=0: wt + UNSCALED GEMM1 (no edge-prologue dependency)
    cudaEventRecord(evFork, 0);
    cudaStreamWaitEvent(sA, evFork, 0);
    wt_kernel<<<128, 256, 0, sA>>>(W1, W2);
    gemm_tc_kernel<1><<<782, 256, GEMM_SMEM_BYTES, sA>>>(x, 0, n);  // || hist_scatter

    // main branch: one-pass CSR build
    hist_scatter_kernel<<<(nedges / 4 + 255) / 256, 256>>>(ei, nedges);
    cudaEventRecord(evHist, 0);

    // aux: fused dinv/deg/clean + scale g_h (needs hist + GEMM1)
    cudaStreamWaitEvent(sA, evHist, 0);
    scale_h_kernel<<<(n * 16 + 255) / 256, 256, 0, sA>>>(n);
    cudaEventRecord(evScaled, sA);

    // main: SpMM1 split at ROW_SPLIT so GEMM2_lo can start early on aux
    cudaStreamWaitEvent(0, evScaled, 0);
    spmm_kernel<1><<<spmm_grid(ROW_SPLIT), 256>>>(b1, nullptr, 0, ROW_SPLIT);
    cudaEventRecord(evS1lo, 0);
    spmm_kernel<1><<<spmm_grid(n - ROW_SPLIT), 256>>>(b1, nullptr, ROW_SPLIT, n);
    cudaEventRecord(evS1hi, 0);

    // aux: GEMM2 halves (row-block-local in g_buf)
    cudaStreamWaitEvent(sA, evS1lo, 0);
    gemm_tc_kernel<2><<<391, 256, GEMM_SMEM_BYTES, sA>>>(nullptr, 0, n);
    cudaStreamWaitEvent(sA, evS1hi, 0);
    gemm_tc_kernel<2><<<391, 256, GEMM_SMEM_BYTES, sA>>>(nullptr, 391, n);
    cudaEventRecord(evG2, sA);

    // main: final SpMM (needs all of g_h)
    cudaStreamWaitEvent(0, evG2, 0);
    spmm_kernel<2><<<spmm_grid(n), 256>>>(b2, out, 0, n);
}